// round 4
// baseline (speedup 1.0000x reference)
#include <cuda_runtime.h>
#include <cstring>

#define Bn 512
#define Tn 512
#define Nn 64
#define NT 128   // threads per block

__device__ __forceinline__ unsigned long long fma2(unsigned long long a,
                                                   unsigned long long b,
                                                   unsigned long long c) {
    unsigned long long d;
    asm("fma.rn.f32x2 %0, %1, %2, %3;" : "=l"(d) : "l"(a), "l"(b), "l"(c));
    return d;
}

__device__ __forceinline__ unsigned long long pack2(float x, float y) {
    float2 f; f.x = x; f.y = y;
    unsigned long long u;
    memcpy(&u, &f, 8);
    return u;
}

__global__ void __launch_bounds__(NT) crf_kernel(
    const float* __restrict__ inp,    // [B,T,N]
    const float* __restrict__ trans,  // [N,N]
    const int*   __restrict__ tags,   // [B,T]
    const int*   __restrict__ lens,   // [B]
    float*       __restrict__ out)    // [512 (+4096)]
{
    const int b = blockIdx.x;
    const int k = threadIdx.x;

    if (b >= Bn) {
        int idx = (b - Bn) * NT + k;
        out[Bn + idx] = trans[idx];
        return;
    }

    const int c = k >> 1;   // column (output tag) 0..63
    const int h = k & 1;    // i-half 0/1

    __shared__ float pbuf[2][Nn];
    __shared__ float sred[4];
    __shared__ float qfin[Nn];

    const int L    = lens[b];
    const int last = (L - 1) > 0 ? (L - 1) : 0;
    const long baseBT = (long)b * Tn;
    const float* __restrict__ erow = inp + baseBT * Nn;

    // ---------------- sequence score (parallel over t, 128 threads) ----------
    float s = 0.f;
    for (int t = k; t < Tn; t += NT) {
        if (t < L) {
            int tg = tags[baseBT + t];
            s += erow[t * Nn + tg];
            if (t >= 1) {
                int tp = tags[baseBT + t - 1];
                s += trans[tp * Nn + tg];
            }
        }
    }
    #pragma unroll
    for (int o = 16; o > 0; o >>= 1)
        s += __shfl_down_sync(0xffffffffu, s, o);
    if ((k & 31) == 0) sred[k >> 5] = s;

    // ---------------- E half-column: exp(trans[h*32+i, c]), i=0..31 ----------
    unsigned long long E2[16];
    #pragma unroll
    for (int m = 0; m < 16; m++) {
        float e0 = __expf(trans[(h * 32 + 2 * m)     * Nn + c]);
        float e1 = __expf(trans[(h * 32 + 2 * m + 1) * Nn + c]);
        E2[m] = pack2(e0, e1);
    }

    // ---------------- forward recursion (linear space, 2^-k rescale) ---------
    float q = __expf(erow[c]);        // q_0 for column c (both halves compute)
    if (h == 0) pbuf[0][c] = q;
    int K = 0;
    int buf = 0;

#define STEP(EEMIT)                                                       \
    do {                                                                  \
        __syncthreads();                                                  \
        const float4* p4 = reinterpret_cast<const float4*>(pbuf[buf]) +   \
                           h * 8;                                         \
        unsigned long long a0 = 0ull, a1 = 0ull, a2 = 0ull, a3 = 0ull;    \
        float4 v0 = p4[0];                                                \
        {                                                                 \
            float4 pw = p4[1];                                            \
            a0 = fma2(pack2(v0.x, v0.y), E2[0], a0);                      \
            a1 = fma2(pack2(v0.z, v0.w), E2[1], a1);                      \
            a2 = fma2(pack2(pw.x, pw.y), E2[2], a2);                      \
            a3 = fma2(pack2(pw.z, pw.w), E2[3], a3);                      \
        }                                                                 \
        _Pragma("unroll")                                                 \
        for (int m = 2; m < 8; m += 2) {                                  \
            float4 pv = p4[m];                                            \
            float4 pw = p4[m + 1];                                        \
            a0 = fma2(pack2(pv.x, pv.y), E2[2 * m + 0], a0);              \
            a1 = fma2(pack2(pv.z, pv.w), E2[2 * m + 1], a1);              \
            a2 = fma2(pack2(pw.x, pw.y), E2[2 * m + 2], a2);              \
            a3 = fma2(pack2(pw.z, pw.w), E2[2 * m + 3], a3);              \
        }                                                                 \
        unsigned long long s01, s23, s03;                                 \
        asm("add.rn.f32x2 %0, %1, %2;" : "=l"(s01) : "l"(a0), "l"(a1));   \
        asm("add.rn.f32x2 %0, %1, %2;" : "=l"(s23) : "l"(a2), "l"(a3));   \
        asm("add.rn.f32x2 %0, %1, %2;" : "=l"(s03) : "l"(s01), "l"(s23)); \
        float2 fs; memcpy(&fs, &s03, 8);                                  \
        float Sh = fs.x + fs.y;                                           \
        float S = Sh + __shfl_xor_sync(0xffffffffu, Sh, 1);               \
        int eb = (__float_as_int(v0.x) >> 23) & 0xFF;                     \
        eb = eb < 64 ? 64 : (eb > 190 ? 190 : eb);                        \
        const float sc = __int_as_float((254 - eb) << 23);                \
        K += eb - 127;                                                    \
        q = S * (EEMIT) * sc;                                             \
        if (h == 0) pbuf[buf ^ 1][c] = q;                                 \
        buf ^= 1;                                                         \
    } while (0)

#define EMLOAD(ROW) erow[(((ROW) < Tn - 1) ? (ROW) : (Tn - 1)) * Nn + c]

    // raw emission pipeline for column c (rows t..t+3)
    float c0 = EMLOAD(1), c1 = EMLOAD(2), c2 = EMLOAD(3), c3 = EMLOAD(4);

    int t = 1;
    for (; t + 3 <= last; t += 4) {
        float n0 = EMLOAD(t + 4);
        float n1 = EMLOAD(t + 5);
        float n2 = EMLOAD(t + 6);
        float n3 = EMLOAD(t + 7);
        float x0 = __expf(c0), x1 = __expf(c1), x2 = __expf(c2), x3 = __expf(c3);
        STEP(x0);
        STEP(x1);
        STEP(x2);
        STEP(x3);
        c0 = n0; c1 = n1; c2 = n2; c3 = n3;
    }
    if (t <= last) { float x = __expf(c0); STEP(x); t++; }
    if (t <= last) { float x = __expf(c1); STEP(x); t++; }
    if (t <= last) { float x = __expf(c2); STEP(x); t++; }

#undef STEP
#undef EMLOAD

    // ---------------- final log-normalizer ----------------
    __syncthreads();
    if (h == 0) qfin[c] = q;          // K identical across even threads
    __syncthreads();
    if (k == 0) {
        float ss = 0.f;
        #pragma unroll
        for (int i = 0; i < Nn; i++) ss += qfin[i];
        const float LN2_HI = 0.693145751953125f;
        const float LN2_LO = 1.428606765330187e-06f;
        const float Kf = (float)K;
        const float lognorm = fmaf(Kf, LN2_LO, fmaf(Kf, LN2_HI, __logf(ss)));
        const float seqscore = (sred[0] + sred[1]) + (sred[2] + sred[3]);
        out[b] = seqscore - lognorm;
    }
}

extern "C" void kernel_launch(void* const* d_in, const int* in_sizes, int n_in,
                              void* d_out, int out_size) {
    const float* inp   = (const float*)d_in[0];
    const float* trans = (const float*)d_in[1];
    const int*   tags  = (const int*)d_in[2];
    const int*   lens  = (const int*)d_in[3];
    float* out = (float*)d_out;

    int nblocks = Bn;
    if (out_size >= Bn + Nn * Nn) nblocks += (Nn * Nn) / NT;   // 32 copy blocks
    crf_kernel<<<nblocks, NT>>>(inp, trans, tags, lens, out);
}

// round 6
// speedup vs baseline: 1.2047x; 1.2047x over previous
#include <cuda_runtime.h>
#include <cstring>

#define Bn 512
#define Tn 512
#define Nn 64
#define NT 32   // single warp per block

typedef unsigned long long ull;

__device__ __forceinline__ ull fma2(ull a, ull b, ull c) {
    ull d;
    asm("fma.rn.f32x2 %0, %1, %2, %3;" : "=l"(d) : "l"(a), "l"(b), "l"(c));
    return d;
}

__device__ __forceinline__ ull pack2(float x, float y) {
    float2 f; f.x = x; f.y = y;
    ull u;
    memcpy(&u, &f, 8);
    return u;
}

__global__ void __launch_bounds__(NT) crf_kernel(
    const float* __restrict__ inp,    // [B,T,N]
    const float* __restrict__ trans,  // [N,N]
    const int*   __restrict__ tags,   // [B,T]
    const int*   __restrict__ lens,   // [B]
    float*       __restrict__ out)    // [512 (+4096)]
{
    const int b = blockIdx.x;
    const int l = threadIdx.x;

    if (b >= Bn) {
        int idx = (b - Bn) * NT + l;
        out[Bn + idx] = trans[idx];
        return;
    }

    const int cA = 2 * l;
    const int cB = 2 * l + 1;

    const int L    = lens[b];
    const int last = (L - 1) > 0 ? (L - 1) : 0;
    const long baseBT = (long)b * Tn;
    const float* __restrict__ erow = inp + baseBT * Nn;

    // ---------------- sequence score (parallel over t, warp reduce) ----------
    float s = 0.f;
    for (int t = l; t < Tn; t += NT) {
        if (t < L) {
            int tg = tags[baseBT + t];
            s += erow[t * Nn + tg];
            if (t >= 1) {
                int tp = tags[baseBT + t - 1];
                s += trans[tp * Nn + tg];
            }
        }
    }
    #pragma unroll
    for (int o = 16; o > 0; o >>= 1)
        s += __shfl_down_sync(0xffffffffu, s, o);
    const float seqscore = s;   // valid in lane 0

    // ---------------- E columns for cA, cB: packed over i-pairs --------------
    // EA[i] = (exp(trans[2i][cA]), exp(trans[2i+1][cA]))
    ull EA[32], EB[32];
    #pragma unroll
    for (int i = 0; i < 32; i++) {
        float a0 = __expf(trans[(2 * i)     * Nn + cA]);
        float a1 = __expf(trans[(2 * i + 1) * Nn + cA]);
        float b0v = __expf(trans[(2 * i)     * Nn + cB]);
        float b1v = __expf(trans[(2 * i + 1) * Nn + cB]);
        EA[i] = pack2(a0, a1);
        EB[i] = pack2(b0v, b1v);
    }

    // ---------------- forward recursion: register-resident, shuffle matvec ---
    float q0 = __expf(erow[cA]);   // q_0[2l]
    float q1 = __expf(erow[cB]);   // q_0[2l+1]
    int K = 0;

    // one step; XA/XB = exp(emission) for columns cA/cB
#define STEP(XA, XB)                                                         \
    do {                                                                     \
        ull a0 = 0ull, a1 = 0ull, b0 = 0ull, b1 = 0ull;                      \
        float plo0 = __shfl_sync(0xffffffffu, q0, 0);                        \
        float phi0 = __shfl_sync(0xffffffffu, q1, 0);                        \
        int eb = (__float_as_int(plo0) >> 23) & 0xFF;                        \
        eb = eb < 64 ? 64 : (eb > 190 ? 190 : eb);                           \
        const float sc = __int_as_float((254 - eb) << 23);                   \
        K += eb - 127;                                                       \
        {                                                                    \
            ull pp = pack2(plo0, phi0);                                      \
            a0 = fma2(pp, EA[0], a0);                                        \
            b0 = fma2(pp, EB[0], b0);                                        \
        }                                                                    \
        _Pragma("unroll")                                                    \
        for (int i = 1; i < 32; i++) {                                       \
            float plo = __shfl_sync(0xffffffffu, q0, i);                     \
            float phi = __shfl_sync(0xffffffffu, q1, i);                     \
            ull pp = pack2(plo, phi);                                        \
            if (i & 1) { a1 = fma2(pp, EA[i], a1); b1 = fma2(pp, EB[i], b1); }\
            else       { a0 = fma2(pp, EA[i], a0); b0 = fma2(pp, EB[i], b0); }\
        }                                                                    \
        ull sa, sb;                                                          \
        asm("add.rn.f32x2 %0, %1, %2;" : "=l"(sa) : "l"(a0), "l"(a1));       \
        asm("add.rn.f32x2 %0, %1, %2;" : "=l"(sb) : "l"(b0), "l"(b1));       \
        float2 fa, fb;                                                       \
        memcpy(&fa, &sa, 8);                                                 \
        memcpy(&fb, &sb, 8);                                                 \
        q0 = (XA) * (fa.x + fa.y) * sc;                                      \
        q1 = (XB) * (fb.x + fb.y) * sc;                                      \
    } while (0)

    // emission row (two adjacent floats for cA,cB), clamped
#define EMLOAD(ROW)                                                          \
    (*reinterpret_cast<const float2*>(                                       \
        erow + ((((ROW) < Tn - 1) ? (ROW) : (Tn - 1)) * Nn) + cA))

    float2 c0 = EMLOAD(1), c1 = EMLOAD(2), c2 = EMLOAD(3), c3 = EMLOAD(4);

    int t = 1;
    for (; t + 3 <= last; t += 4) {
        // next chunk's independent loads (hidden behind 4 steps)
        float2 n0 = EMLOAD(t + 4);
        float2 n1 = EMLOAD(t + 5);
        float2 n2 = EMLOAD(t + 6);
        float2 n3 = EMLOAD(t + 7);
        // off-critical-path emission exponentials
        float x0a = __expf(c0.x), x0b = __expf(c0.y);
        float x1a = __expf(c1.x), x1b = __expf(c1.y);
        float x2a = __expf(c2.x), x2b = __expf(c2.y);
        float x3a = __expf(c3.x), x3b = __expf(c3.y);
        STEP(x0a, x0b);
        STEP(x1a, x1b);
        STEP(x2a, x2b);
        STEP(x3a, x3b);
        c0 = n0; c1 = n1; c2 = n2; c3 = n3;
    }
    if (t <= last) { float xa = __expf(c0.x), xb = __expf(c0.y); STEP(xa, xb); t++; }
    if (t <= last) { float xa = __expf(c1.x), xb = __expf(c1.y); STEP(xa, xb); t++; }
    if (t <= last) { float xa = __expf(c2.x), xb = __expf(c2.y); STEP(xa, xb); t++; }

#undef STEP
#undef EMLOAD

    // ---------------- final log-normalizer (warp reduce) ----------------
    float ssum = q0 + q1;
    #pragma unroll
    for (int o = 16; o > 0; o >>= 1)
        ssum += __shfl_down_sync(0xffffffffu, ssum, o);

    if (l == 0) {
        const float LN2_HI = 0.693145751953125f;
        const float LN2_LO = 1.428606765330187e-06f;
        const float Kf = (float)K;
        const float lognorm = fmaf(Kf, LN2_LO, fmaf(Kf, LN2_HI, __logf(ssum)));
        out[b] = seqscore - lognorm;
    }
}

extern "C" void kernel_launch(void* const* d_in, const int* in_sizes, int n_in,
                              void* d_out, int out_size) {
    const float* inp   = (const float*)d_in[0];
    const float* trans = (const float*)d_in[1];
    const int*   tags  = (const int*)d_in[2];
    const int*   lens  = (const int*)d_in[3];
    float* out = (float*)d_out;

    int nblocks = Bn;
    if (out_size >= Bn + Nn * Nn) nblocks += (Nn * Nn) / NT;   // 128 copy blocks
    crf_kernel<<<nblocks, NT>>>(inp, trans, tags, lens, out);
}

// round 7
// speedup vs baseline: 1.4317x; 1.1885x over previous
#include <cuda_runtime.h>
#include <cstring>

#define Bn 512
#define Tn 512
#define Nn 64
#define NT 32   // single warp per block

typedef unsigned long long ull;

__device__ __forceinline__ ull fma2(ull a, ull b, ull c) {
    ull d;
    asm("fma.rn.f32x2 %0, %1, %2, %3;" : "=l"(d) : "l"(a), "l"(b), "l"(c));
    return d;
}

__device__ __forceinline__ ull add2(ull a, ull b) {
    ull d;
    asm("add.rn.f32x2 %0, %1, %2;" : "=l"(d) : "l"(a), "l"(b));
    return d;
}

__device__ __forceinline__ ull pack2(float x, float y) {
    float2 f; f.x = x; f.y = y;
    ull u;
    memcpy(&u, &f, 8);
    return u;
}

__global__ void __launch_bounds__(NT) crf_kernel(
    const float* __restrict__ inp,    // [B,T,N]
    const float* __restrict__ trans,  // [N,N]
    const int*   __restrict__ tags,   // [B,T]
    const int*   __restrict__ lens,   // [B]
    float*       __restrict__ out)    // [512 + 4096]
{
    const int b = blockIdx.x;
    const int l = threadIdx.x;

    // fused transition_params copy: 8 elements per block (512*8 = 4096)
    if (l < 8) {
        int idx = b * 8 + l;
        out[Bn + idx] = trans[idx];
    }

    const int cA = 2 * l;
    const int cB = 2 * l + 1;

    __shared__ float pbuf[2][Nn];

    const int L    = lens[b];
    const int last = (L - 1) > 0 ? (L - 1) : 0;
    const long baseBT = (long)b * Tn;
    const float* __restrict__ erow = inp + baseBT * Nn;

    // ---------------- sequence score (parallel over t, warp reduce) ----------
    float s = 0.f;
    for (int t = l; t < Tn; t += NT) {
        if (t < L) {
            int tg = tags[baseBT + t];
            s += erow[t * Nn + tg];
            if (t >= 1) {
                int tp = tags[baseBT + t - 1];
                s += trans[tp * Nn + tg];
            }
        }
    }
    #pragma unroll
    for (int o = 16; o > 0; o >>= 1)
        s += __shfl_down_sync(0xffffffffu, s, o);
    const float seqscore = s;   // valid in lane 0

    // ---------------- E columns for cA, cB, packed over i-pairs --------------
    // EA[i] = (exp(trans[2i][cA]), exp(trans[2i+1][cA]))
    ull EA[32], EB[32];
    #pragma unroll
    for (int i = 0; i < 32; i++) {
        float a0 = __expf(trans[(2 * i)     * Nn + cA]);
        float a1 = __expf(trans[(2 * i + 1) * Nn + cA]);
        float b0 = __expf(trans[(2 * i)     * Nn + cB]);
        float b1 = __expf(trans[(2 * i + 1) * Nn + cB]);
        EA[i] = pack2(a0, a1);
        EB[i] = pack2(b0, b1);
    }

    // ---------------- forward recursion: smem broadcast, syncwarp only -------
    float q0 = __expf(erow[cA]);
    float q1 = __expf(erow[cB]);
    *reinterpret_cast<float2*>(&pbuf[0][cA]) = make_float2(q0, q1);
    int K = 0;
    int buf = 0;

    // one step; XA/XB = exp(emission) for columns cA/cB
#define STEP(XA, XB)                                                         \
    do {                                                                     \
        __syncwarp();                                                        \
        const float4* p4 = reinterpret_cast<const float4*>(pbuf[buf]);       \
        ull aA0, aA1, aB0, aB1;                                              \
        float4 v0 = p4[0];                                                   \
        int eb = (__float_as_int(v0.x) >> 23) & 0xFF;                        \
        eb = eb < 64 ? 64 : (eb > 190 ? 190 : eb);                           \
        const float sc = __int_as_float((254 - eb) << 23);                   \
        K += eb - 127;                                                       \
        {                                                                    \
            ull plo = pack2(v0.x, v0.y);                                     \
            ull phi = pack2(v0.z, v0.w);                                     \
            aA0 = fma2(plo, EA[0], 0ull);                                    \
            aA1 = fma2(phi, EA[1], 0ull);                                    \
            aB0 = fma2(plo, EB[0], 0ull);                                    \
            aB1 = fma2(phi, EB[1], 0ull);                                    \
        }                                                                    \
        _Pragma("unroll")                                                    \
        for (int m = 1; m < 16; m++) {                                       \
            float4 v = p4[m];                                                \
            ull plo = pack2(v.x, v.y);                                       \
            ull phi = pack2(v.z, v.w);                                       \
            aA0 = fma2(plo, EA[2 * m],     aA0);                             \
            aA1 = fma2(phi, EA[2 * m + 1], aA1);                             \
            aB0 = fma2(plo, EB[2 * m],     aB0);                             \
            aB1 = fma2(phi, EB[2 * m + 1], aB1);                             \
        }                                                                    \
        ull sA = add2(aA0, aA1);                                             \
        ull sB = add2(aB0, aB1);                                             \
        float2 fA, fB;                                                       \
        memcpy(&fA, &sA, 8);                                                 \
        memcpy(&fB, &sB, 8);                                                 \
        q0 = (XA) * (fA.x + fA.y) * sc;                                      \
        q1 = (XB) * (fB.x + fB.y) * sc;                                      \
        *reinterpret_cast<float2*>(&pbuf[buf ^ 1][cA]) = make_float2(q0, q1);\
        buf ^= 1;                                                            \
    } while (0)

    // emission row (two adjacent floats for cA,cB), clamped row index
#define EMLOAD(ROW)                                                          \
    (*reinterpret_cast<const float2*>(                                       \
        erow + ((((ROW) < Tn - 1) ? (ROW) : (Tn - 1)) * Nn) + cA))

    float2 c0 = EMLOAD(1), c1 = EMLOAD(2), c2 = EMLOAD(3), c3 = EMLOAD(4);

    int t = 1;
    for (; t + 3 <= last; t += 4) {
        // next chunk's independent loads (hidden behind 4 steps)
        float2 n0 = EMLOAD(t + 4);
        float2 n1 = EMLOAD(t + 5);
        float2 n2 = EMLOAD(t + 6);
        float2 n3 = EMLOAD(t + 7);
        // off-critical-path emission exponentials
        float x0a = __expf(c0.x), x0b = __expf(c0.y);
        float x1a = __expf(c1.x), x1b = __expf(c1.y);
        float x2a = __expf(c2.x), x2b = __expf(c2.y);
        float x3a = __expf(c3.x), x3b = __expf(c3.y);
        STEP(x0a, x0b);
        STEP(x1a, x1b);
        STEP(x2a, x2b);
        STEP(x3a, x3b);
        c0 = n0; c1 = n1; c2 = n2; c3 = n3;
    }
    if (t <= last) { float xa = __expf(c0.x), xb = __expf(c0.y); STEP(xa, xb); t++; }
    if (t <= last) { float xa = __expf(c1.x), xb = __expf(c1.y); STEP(xa, xb); t++; }
    if (t <= last) { float xa = __expf(c2.x), xb = __expf(c2.y); STEP(xa, xb); t++; }

#undef STEP
#undef EMLOAD

    // ---------------- final log-normalizer (warp reduce) ----------------
    float ssum = q0 + q1;
    #pragma unroll
    for (int o = 16; o > 0; o >>= 1)
        ssum += __shfl_down_sync(0xffffffffu, ssum, o);

    if (l == 0) {
        const float LN2_HI = 0.693145751953125f;
        const float LN2_LO = 1.428606765330187e-06f;
        const float Kf = (float)K;
        const float lognorm = fmaf(Kf, LN2_LO, fmaf(Kf, LN2_HI, __logf(ssum)));
        out[b] = seqscore - lognorm;
    }
}

extern "C" void kernel_launch(void* const* d_in, const int* in_sizes, int n_in,
                              void* d_out, int out_size) {
    const float* inp   = (const float*)d_in[0];
    const float* trans = (const float*)d_in[1];
    const int*   tags  = (const int*)d_in[2];
    const int*   lens  = (const int*)d_in[3];
    float* out = (float*)d_out;

    crf_kernel<<<Bn, NT>>>(inp, trans, tags, lens, out);
}